// round 14
// baseline (speedup 1.0000x reference)
#include <cuda_runtime.h>
#include <cuda_fp16.h>
#include <cstdint>

#define H0c 100
#define W0c 152
#define H1c 50
#define W1c 76
#define HW0 (H0c*W0c)          // 15200
#define HW1 (H1c*W1c)          // 3800
#define NB 2
#define CIN 256
#define DYNC 34
#define CLSC 720
#define NCLS 80
#define NPIX (NB*(HW0+HW1))    // 38000
#define NPIXP 38016            // 297*128
#define OCP 768
#define KDYN2 2304             // 9*256 (B_hi)

// padded (H+2, W+2) dims for dyn GEMM A-matrix
#define PH0 102
#define PW0 154
#define PH1 52
#define PW1 78
#define PAD0TOT (NB*PH0*PW0)            // 31416
#define PADTOT (PAD0TOT + NB*PH1*PW1)   // 39528

// border enumeration
#define BORD0 (2*PW0 + 2*(PH0-2))       // 508
#define BORD1 (2*PW1 + 2*(PH1-2))       // 256
#define NBORD (NB*BORD0 + NB*BORD1)     // 1528

#define O_CLS0 0
#define O_CLS1 (NB*NCLS*HW0)
#define O_CO0  (O_CLS1 + NB*NCLS*HW1)
#define O_CO1  (O_CO0 + NB*4*HW0)
#define O_RB0  (O_CO1 + NB*4*HW1)
#define O_RB1  (O_RB0 + NB*4*HW0)

// split_w index ranges
#define SW_DYN (64*9*256)               // 147456
#define SW_CLS (SW_DYN + OCP*CIN)       // 344064
#define SW_BORD (SW_CLS + NBORD*32)     // g_regS 256-wide -> 32 uint4/pix
#define SW_TOTAL (SW_BORD + 16*32)      // featS tail (16 pix * 32 uint4)

// ---------------- scratch ----------------
__device__ float g_pred[NPIX*DYNC];
__device__ float g_regmap[NPIX*4];
__device__ __half g_clsmap[(size_t)NPIXP*CLSC];
__device__ __align__(16) __half g_featS[(size_t)NPIXP*256];      // cls A hi [pix][256]
__device__ __align__(16) __half g_wclsS[(size_t)OCP*256];        // cls B_hi [oc][256]
__device__ __align__(16) __half g_regS[(size_t)PADTOT*256];      // dyn A hi [padpix][256]
__device__ __align__(16) __half g_wdynS[64*KDYN2];               // dyn B_hi [oc][9*256]

// ---------------- PTX helpers ----------------
__device__ __forceinline__ void cpa16(uint32_t d, const void* s) {
    asm volatile("cp.async.cg.shared.global [%0],[%1],16;\n" :: "r"(d), "l"(s));
}
#define CP_COMMIT() asm volatile("cp.async.commit_group;\n")
#define CP_WAIT1()  asm volatile("cp.async.wait_group 1;\n")
#define CP_WAIT0()  asm volatile("cp.async.wait_group 0;\n")

__device__ __forceinline__ void ldm_x4(uint32_t& r0, uint32_t& r1,
                                       uint32_t& r2, uint32_t& r3, uint32_t addr) {
    asm volatile("ldmatrix.sync.aligned.m8n8.x4.shared.b16 {%0,%1,%2,%3},[%4];"
                 : "=r"(r0), "=r"(r1), "=r"(r2), "=r"(r3) : "r"(addr));
}
__device__ __forceinline__ void mma_f16(float* c, uint32_t a0, uint32_t a1,
                                        uint32_t a2, uint32_t a3,
                                        uint32_t b0, uint32_t b1) {
    asm volatile("mma.sync.aligned.m16n8k16.row.col.f32.f16.f16.f32 "
                 "{%0,%1,%2,%3},{%4,%5,%6,%7},{%8,%9},{%0,%1,%2,%3};"
                 : "+f"(c[0]), "+f"(c[1]), "+f"(c[2]), "+f"(c[3])
                 : "r"(a0), "r"(a1), "r"(a2), "r"(a3), "r"(b0), "r"(b1));
}

// ---------------- merged weight split + border/tail zero ----------------
__global__ void split_w_kernel(const float* __restrict__ dyn_w,
                               const float* __restrict__ reg_w,
                               const float* __restrict__ cls_w) {
    int i = blockIdx.x*blockDim.x + threadIdx.x;
    if (i < SW_DYN) {
        int oc = i / (9*256);
        int rem = i - oc*9*256;
        int p = rem >> 8, c = rem & 255;
        float v = 0.f;
        if (oc < DYNC) v = dyn_w[(oc*CIN + c)*9 + p];
        else if (oc < 38 && p == 4) v = reg_w[(oc - DYNC)*CIN + c];
        g_wdynS[(size_t)oc*KDYN2 + p*256 + c] = __float2half(v);
    } else if (i < SW_CLS) {
        int j = i - SW_DYN;
        int oc = j >> 8, c = j & 255;
        float v = (oc < CLSC) ? cls_w[j] : 0.f;
        g_wclsS[(size_t)oc*256 + c] = __float2half(v);
    } else if (i < SW_BORD) {
        int b = i - SW_CLS;
        int bp = b >> 5, u = b & 31;
        int y, x, padBase, PWl;
        if (bp < NB*BORD0) {
            int n = bp / BORD0, k = bp - n*BORD0;
            padBase = n*PH0*PW0; PWl = PW0;
            if (k < PW0) { y = 0; x = k; }
            else if (k < 2*PW0) { y = PH0-1; x = k - PW0; }
            else { int k2 = k - 2*PW0; y = 1 + (k2 >> 1); x = (k2 & 1) ? (PW0-1) : 0; }
        } else {
            int b2 = bp - NB*BORD0;
            int n = b2 / BORD1, k = b2 - n*BORD1;
            padBase = PAD0TOT + n*PH1*PW1; PWl = PW1;
            if (k < PW1) { y = 0; x = k; }
            else if (k < 2*PW1) { y = PH1-1; x = k - PW1; }
            else { int k2 = k - 2*PW1; y = 1 + (k2 >> 1); x = (k2 & 1) ? (PW1-1) : 0; }
        }
        ((uint4*)g_regS)[(size_t)(padBase + y*PWl + x)*32 + u] = make_uint4(0,0,0,0);
    } else if (i < SW_TOTAL) {
        int j = i - SW_BORD;
        ((uint4*)g_featS)[(size_t)NPIX*32 + j] = make_uint4(0,0,0,0);
    }
}

// ---------------- merged feature transpose+split, 64-ch tiles, half2 writes ----------------
__global__ void split_all_kernel(const float* __restrict__ reg0,
                                 const float* __restrict__ reg1,
                                 const float* __restrict__ cls0,
                                 const float* __restrict__ cls1)
{
    __shared__ float t[64][33];
    int src = blockIdx.z >> 1;
    int n   = blockIdx.z & 1;
    int lvl = src & 1;
    int HW  = lvl ? HW1 : HW0;
    int pixbase = blockIdx.x*32;
    if (pixbase >= HW) return;
    const float* in = (src == 0) ? reg0 : (src == 1) ? reg1 : (src == 2) ? cls0 : cls1;

    int tx = threadIdx.x, ty = threadIdx.y;
    int chbase = blockIdx.y*64;
    int pix = pixbase + tx;
    #pragma unroll
    for (int j = 0; j < 8; j++) {
        int ch = ty + j*8;
        t[ch][tx] = (pix < HW) ? in[((size_t)(n*CIN + chbase + ch))*HW + pix] : 0.f;
    }
    __syncthreads();

    int u = ty*32 + tx;
    if (src >= 2) {   // cls -> g_featS (hi only)
        int base = lvl ? (NB*HW0 + n*HW1) : (n*HW0);
        #pragma unroll
        for (int k = 0; k < 4; k++) {
            int idx = u + k*256;
            int pr = idx >> 5, pi = idx & 31;
            int opix = pixbase + pr;
            if (opix < HW) {
                float v0 = t[pi*2][pr], v1 = t[pi*2+1][pr];
                __half* d = g_featS + (size_t)(base + opix)*256 + chbase + pi*2;
                *(__half2*)d = __halves2half2(__float2half(v0), __float2half(v1));
            }
        }
    } else {          // reg -> g_regS (padded, hi only)
        int W  = lvl ? W1c : W0c;
        int PW = lvl ? PW1 : PW0;
        int padBase = lvl ? (PAD0TOT + n*PH1*PW1) : (n*PH0*PW0);
        #pragma unroll
        for (int k = 0; k < 4; k++) {
            int idx = u + k*256;
            int pr = idx >> 5, pi = idx & 31;
            int opix = pixbase + pr;
            if (opix < HW) {
                int y = opix / W, x = opix - y*W;
                float v0 = t[pi*2][pr], v1 = t[pi*2+1][pr];
                __half* d = g_regS + (size_t)(padBase + (y+1)*PW + x + 1)*256 + chbase + pi*2;
                *(__half2*)d = __halves2half2(__float2half(v0), __float2half(v1));
            }
        }
    }
}

// ---------------- unified MMA kernel (128 threads, 4 warps, 3 CTAs/SM) ----------------
#define RS 144
#define A_STG (128*RS)       // 18432
#define DYN_B_STG (64*RS)    // 9216
#define CLS_B_STG (128*RS)   // 18432
#define UK_SMEM (2*A_STG + 2*CLS_B_STG)   // 73728

__global__ void __launch_bounds__(128, 3) mma_all_kernel(const float* __restrict__ dyn_b)
{
    extern __shared__ __align__(16) char sm[];
    int tid = threadIdx.x;
    int lane = tid & 31, wid = tid >> 5;
    int wm = wid & 1, wn = wid >> 1;
    int rA = tid >> 3, cA = tid & 7;

    uint32_t AsB = (uint32_t)__cvta_generic_to_shared(sm);

    if (blockIdx.x < 330) {
        // ---------- dyn: 128x64 tile, warp 64x32; K = 9*256 in 36 chunks ----------
        int bid = blockIdx.x;
        int lvl, n, tX, tY;
        if (bid < 260) { lvl = 0; n = bid/130; int t = bid - n*130; tY = t/10; tX = t - tY*10; }
        else { int b = bid - 260; lvl = 1; n = b/35; int t = b - n*35; tY = t/5; tX = t - tY*5; }
        int H  = lvl ? H1c : H0c;
        int W  = lvl ? W1c : W0c;
        int PW = lvl ? PW1 : PW0;
        int padBase = lvl ? (PAD0TOT + n*PH1*PW1) : (n*PH0*PW0);
        int gbase   = lvl ? (NB*HW0 + n*HW1) : (n*HW0);
        int y0 = tY*8, x0 = tX*16;

        int aPix[8];
        #pragma unroll
        for (int j = 0; j < 8; j++) {
            int r = rA + 16*j;
            int y = y0 + (r >> 4); if (y >= H) y = H - 1;
            int x = x0 + (r & 15); if (x >= W) x = W - 1;
            aPix[j] = padBase + (y + 1)*PW + x + 1;
        }

        uint32_t BsB = AsB + 2*A_STG;

        float acc[4][4][4];
        #pragma unroll
        for (int f = 0; f < 4; f++)
            #pragma unroll
            for (int j = 0; j < 4; j++)
                #pragma unroll
                for (int e = 0; e < 4; e++) acc[f][j][e] = 0.f;

        // zero smem B rows 48-63 (both stages); staging never writes them
        for (int z = tid; z < 2*16*9; z += 128) {
            int s = z / (16*9);
            int rr = 48 + ((z - s*16*9) / 9);
            int cc = (z % 9)*16;
            asm volatile("st.shared.v4.b32 [%0], {%1,%1,%1,%1};"
                         :: "r"(BsB + s*DYN_B_STG + (uint32_t)(rr*RS + cc)), "r"(0) : "memory");
        }

        // chunk q: p = q/4, kc = q%4
        #define DYN_LOAD(s, q) do { \
            int p_ = (q) >> 2, kc_ = (q) & 3; \
            int sh_ = (p_/3 - 1)*PW + (p_ - (p_/3)*3 - 1); \
            int ko_ = kc_*64 + cA*8; \
            _Pragma("unroll") \
            for (int j_ = 0; j_ < 8; j_++) \
                cpa16(AsB + (s)*A_STG + (uint32_t)((rA + 16*j_)*RS + cA*16), \
                      g_regS + (size_t)(aPix[j_] + sh_)*256 + ko_); \
            _Pragma("unroll") \
            for (int j_ = 0; j_ < 3; j_++)  /* B rows 0-47; 48-63 stay zero */ \
                cpa16(BsB + (s)*DYN_B_STG + (uint32_t)((rA + 16*j_)*RS + cA*16), \
                      g_wdynS + (size_t)(rA + 16*j_)*KDYN2 + p_*256 + ko_); \
        } while (0)

        __syncthreads();
        DYN_LOAD(0, 0);
        CP_COMMIT();

        #pragma unroll 1
        for (int q = 0; q < 36; q++) {
            int cur = q & 1;
            if (q < 35) {
                DYN_LOAD(cur ^ 1, q + 1);
                CP_COMMIT();
                CP_WAIT1();
            } else {
                CP_WAIT0();
            }
            __syncthreads();

            uint32_t abase = AsB + cur*A_STG + (uint32_t)((wm*64 + (lane & 15))*RS);
            uint32_t bbase = BsB + cur*DYN_B_STG + (uint32_t)((wn*32 + (lane & 15))*RS);
            uint32_t cofs0 = (uint32_t)((lane >> 4)*16);

            #pragma unroll
            for (int kk = 0; kk < 4; kk++) {
                uint32_t co = cofs0 + kk*32;
                uint32_t a[4][4];
                #pragma unroll
                for (int f = 0; f < 4; f++)
                    ldm_x4(a[f][0], a[f][1], a[f][2], a[f][3], abase + f*16*RS + co);
                uint32_t b[2][4];
                #pragma unroll
                for (int g = 0; g < 2; g++)
                    ldm_x4(b[g][0], b[g][1], b[g][2], b[g][3], bbase + g*16*RS + co);
                #pragma unroll
                for (int f = 0; f < 4; f++)
                    #pragma unroll
                    for (int g = 0; g < 2; g++) {
                        mma_f16(acc[f][2*g],   a[f][0], a[f][1], a[f][2], a[f][3],
                                b[g][0], b[g][2]);
                        mma_f16(acc[f][2*g+1], a[f][0], a[f][1], a[f][2], a[f][3],
                                b[g][1], b[g][3]);
                    }
            }
            __syncthreads();
        }

        int rowin = lane >> 2;
        int colin = (lane & 3)*2;
        #pragma unroll
        for (int f = 0; f < 4; f++) {
            #pragma unroll
            for (int half = 0; half < 2; half++) {
                int tr = wm*64 + f*16 + rowin + half*8;
                int y = y0 + (tr >> 4), x = x0 + (tr & 15);
                if (y < H && x < W) {
                    int gp = gbase + y*W + x;
                    #pragma unroll
                    for (int j = 0; j < 4; j++) {
                        int oc = wn*32 + j*8 + colin;
                        float v0 = acc[f][j][half*2];
                        float v1 = acc[f][j][half*2 + 1];
                        if (oc < DYNC) {
                            g_pred[(size_t)gp*DYNC + oc] = v0 + __ldg(dyn_b + oc);
                        } else if (oc < 38) {
                            g_regmap[(size_t)gp*4 + oc - DYNC] = v0;
                        }
                        int oc1 = oc + 1;
                        if (oc1 < DYNC) {
                            g_pred[(size_t)gp*DYNC + oc1] = v1 + __ldg(dyn_b + oc1);
                        } else if (oc1 < 38) {
                            g_regmap[(size_t)gp*4 + oc1 - DYNC] = v1;
                        }
                    }
                }
            }
        }
    } else {
        // ---------- cls: 128x128, warp 64x64; K=256 in 4 chunks ----------
        int bid = blockIdx.x - 330;
        int pixblk = bid % 297;
        int ocblk  = bid / 297;
        int pixbase = pixblk*128;
        int ocbase  = ocblk*128;

        const __half* Ag = g_featS + (size_t)pixbase*256;
        const __half* Bg = g_wclsS + (size_t)ocbase*256;

        uint32_t BsB = AsB + 2*A_STG;

        float acc[4][8][4];
        #pragma unroll
        for (int f = 0; f < 4; f++)
            #pragma unroll
            for (int j = 0; j < 8; j++)
                #pragma unroll
                for (int e = 0; e < 4; e++) acc[f][j][e] = 0.f;

        #define CLS_LOAD(s, bk) do { \
            int k_ = (bk)*64 + cA*8; \
            _Pragma("unroll") \
            for (int j_ = 0; j_ < 8; j_++) { \
                cpa16(AsB + (s)*A_STG + (uint32_t)((rA + 16*j_)*RS + cA*16), \
                      Ag + (size_t)(rA + 16*j_)*256 + k_); \
                cpa16(BsB + (s)*CLS_B_STG + (uint32_t)((rA + 16*j_)*RS + cA*16), \
                      Bg + (size_t)(rA + 16*j_)*256 + k_); \
            } \
        } while (0)

        CLS_LOAD(0, 0);
        CP_COMMIT();

        #pragma unroll 1
        for (int bk = 0; bk < 4; bk++) {
            int cur = bk & 1;
            if (bk < 3) {
                CLS_LOAD(cur ^ 1, bk + 1);
                CP_COMMIT();
                CP_WAIT1();
            } else {
                CP_WAIT0();
            }
            __syncthreads();

            uint32_t abase = AsB + cur*A_STG + (uint32_t)((wm*64 + (lane & 15))*RS);
            uint32_t bbase = BsB + cur*CLS_B_STG + (uint32_t)((wn*64 + (lane & 15))*RS);
            uint32_t cofs0 = (uint32_t)((lane >> 4)*16);

            #pragma unroll
            for (int kk = 0; kk < 4; kk++) {
                uint32_t co = cofs0 + kk*32;
                uint32_t a[4][4];
                #pragma unroll
                for (int f = 0; f < 4; f++)
                    ldm_x4(a[f][0], a[f][1], a[f][2], a[f][3], abase + f*16*RS + co);
                uint32_t b[4][4];
                #pragma unroll
                for (int g = 0; g < 4; g++)
                    ldm_x4(b[g][0], b[g][1], b[g][2], b[g][3], bbase + g*16*RS + co);
                #pragma unroll
                for (int f = 0; f < 4; f++)
                    #pragma unroll
                    for (int g = 0; g < 4; g++) {
                        mma_f16(acc[f][2*g],   a[f][0], a[f][1], a[f][2], a[f][3],
                                b[g][0], b[g][2]);
                        mma_f16(acc[f][2*g+1], a[f][0], a[f][1], a[f][2], a[f][3],
                                b[g][1], b[g][3]);
                    }
            }
            __syncthreads();
        }

        int rowin = lane >> 2;
        int colin = (lane & 3)*2;
        #pragma unroll
        for (int f = 0; f < 4; f++) {
            int pix = pixbase + wm*64 + f*16 + rowin;
            #pragma unroll
            for (int j = 0; j < 8; j++) {
                int oc = ocbase + wn*64 + j*8 + colin;
                if (oc < CLSC) {
                    __half* d0 = g_clsmap + (size_t)pix*CLSC + oc;
                    *(__half2*)d0 = __halves2half2(__float2half(acc[f][j][0]),
                                                   __float2half(acc[f][j][1]));
                    __half* d1 = g_clsmap + (size_t)(pix + 8)*CLSC + oc;
                    *(__half2*)d1 = __halves2half2(__float2half(acc[f][j][2]),
                                                   __float2half(acc[f][j][3]));
                }
            }
        }
    }
}

// ---------------- geometry + reg sampling (both levels, one launch) ----------------
__device__ __forceinline__ float bilin4(const float* __restrict__ rm,
                                        int H, int W, float px, float py, int chn)
{
    px = fminf(fmaxf(px, 0.f), (float)(W - 1));
    py = fminf(fmaxf(py, 0.f), (float)(H - 1));
    float xf = floorf(px), yf = floorf(py);
    float fx = px - xf, fy = py - yf;
    int x0 = (int)xf, y0 = (int)yf;
    int x1 = min(x0 + 1, W - 1), y1 = min(y0 + 1, H - 1);
    float v00 = rm[(y0*W + x0)*4 + chn];
    float v01 = rm[(y0*W + x1)*4 + chn];
    float v10 = rm[(y1*W + x0)*4 + chn];
    float v11 = rm[(y1*W + x1)*4 + chn];
    return v00*(1.f-fx)*(1.f-fy) + v01*fx*(1.f-fy)
         + v10*(1.f-fx)*fy       + v11*fx*fy;
}

__global__ void geom_all_kernel(const float* __restrict__ anchor0,
                                const float* __restrict__ anchor1,
                                float* __restrict__ out)
{
    int t = blockIdx.x*blockDim.x + threadIdx.x;
    if (t >= NPIX) return;
    int lvl = (t >= NB*HW0);
    int H, W, HW, n, rem;
    const float* anchor;
    float *oc_, *orb;
    if (!lvl) {
        HW = HW0; H = H0c; W = W0c;
        n = t / HW0; rem = t - n*HW0;
        anchor = anchor0; oc_ = out + O_CO0; orb = out + O_RB0;
    } else {
        int u = t - NB*HW0;
        HW = HW1; H = H1c; W = W1c;
        n = u / HW1; rem = u - n*HW1;
        anchor = anchor1; oc_ = out + O_CO1; orb = out + O_RB1;
    }

    const float* p = g_pred + (size_t)t*DYNC;
    float x1b = anchor[(n*4 + 0)*HW + rem] + p[0];
    float y1b = anchor[(n*4 + 1)*HW + rem] + p[1];
    float x2b = anchor[(n*4 + 2)*HW + rem] + p[2];
    float y2b = anchor[(n*4 + 3)*HW + rem] + p[3];
    float cx = 0.5f*(x1b + x2b), cy = 0.5f*(y1b + y2b);
    float th_h = (y2b - y1b)*0.25f;
    float th_w = (x2b - x1b)*0.25f;
    float b0 = p[4], b1 = p[5], b2 = p[6], b3 = p[7];
    float bc0 = b0 - (fmaxf(b0 - th_h, 0.f) + fminf(b0 + th_h, 0.f));
    float bc1 = b1 - (fmaxf(b1 - th_w, 0.f) + fminf(b1 + th_w, 0.f));
    float bc2 = b2 - (fmaxf(b2 - th_h, 0.f) + fminf(b2 + th_h, 0.f));
    float bc3 = b3 - (fmaxf(b3 - th_w, 0.f) + fminf(b3 + th_w, 0.f));

    float ptx[4] = {x1b, cx + bc1, x2b, cx + bc3};
    float pty[4] = {cy + bc0, y1b, cy + bc2, y2b};

    const float* rm = g_regmap + (size_t)(lvl ? (NB*HW0 + n*HW1) : (n*HW0))*4;
    float r[4];
    #pragma unroll
    for (int pc = 0; pc < 4; pc++)
        r[pc] = bilin4(rm, H, W, ptx[pc], pty[pc], pc);

    if (lvl) {
        const float* rml = g_regmap + (size_t)n*HW0*4;
        #pragma unroll
        for (int pc = 0; pc < 4; pc++) {
            float rl = 0.5f*bilin4(rml, H0c, W0c, 2.f*ptx[pc], 2.f*pty[pc], pc);
            float al = p[26 + 2*pc], ah = p[27 + 2*pc];
            float m = fmaxf(al, ah);
            float el = expf(al - m), eh = expf(ah - m);
            float inv = 1.f/(el + eh);
            r[pc] = (el*rl + eh*r[pc])*inv;
        }
    }

    oc_[(n*4 + 0)*HW + rem] = x1b;
    oc_[(n*4 + 1)*HW + rem] = y1b;
    oc_[(n*4 + 2)*HW + rem] = x2b;
    oc_[(n*4 + 3)*HW + rem] = y2b;
    orb[(n*4 + 0)*HW + rem] = x1b + r[0];
    orb[(n*4 + 1)*HW + rem] = y1b + r[1];
    orb[(n*4 + 2)*HW + rem] = x2b + r[2];
    orb[(n*4 + 3)*HW + rem] = y2b + r[3];
}

// ---------------- cls sampling: 4 pixels/block, 320 threads ----------------
#define SPB 4
__global__ void __launch_bounds__(SPB*NCLS) cls_sample_kernel(
    const float* __restrict__ cls_b, float* __restrict__ out)
{
    int t = blockIdx.x*SPB + threadIdx.x/NCLS;
    int cls = threadIdx.x % NCLS;
    if (t >= NPIX) return;

    int lvl = (t >= NB*HW0);
    int H, W, HW, n, rem, base;
    const float* coarse;
    float* ob;
    if (!lvl) {
        HW = HW0; H = H0c; W = W0c;
        n = t / HW0; rem = t - n*HW0;
        base = n*HW0;
        coarse = out + O_CO0; ob = out + O_CLS0;
    } else {
        int u = t - NB*HW0;
        HW = HW1; H = H1c; W = W1c;
        n = u / HW1; rem = u - n*HW1;
        base = NB*HW0 + n*HW1;
        coarse = out + O_CO1; ob = out + O_CLS1;
    }

    const float* p = g_pred + (size_t)t*DYNC;
    float x1b = coarse[(n*4 + 0)*HW + rem];
    float y1b = coarse[(n*4 + 1)*HW + rem];
    float x2b = coarse[(n*4 + 2)*HW + rem];
    float y2b = coarse[(n*4 + 3)*HW + rem];
    float X[3] = {x1b, 0.5f*(x1b + x2b), x2b};
    float Y[3] = {y1b, 0.5f*(y1b + y2b), y2b};

    float acc = cls_b[cls];
    const __half* cm = g_clsmap + (size_t)base*CLSC;

    #pragma unroll
    for (int pt = 0; pt < 9; pt++) {
        float px = X[pt/3] + p[8 + 2*pt];
        float py = Y[pt%3] + p[9 + 2*pt];
        px = fminf(fmaxf(px, 0.f), (float)(W - 1));
        py = fminf(fmaxf(py, 0.f), (float)(H - 1));
        float xf = floorf(px), yf = floorf(py);
        float fx = px - xf, fy = py - yf;
        int x0 = (int)xf, y0 = (int)yf;
        int x1i = min(x0 + 1, W - 1), y1i = min(y0 + 1, H - 1);
        int chn = pt*NCLS + cls;
        float v00 = __half2float(__ldg(cm + (size_t)(y0*W  + x0 )*CLSC + chn));
        float v01 = __half2float(__ldg(cm + (size_t)(y0*W  + x1i)*CLSC + chn));
        float v10 = __half2float(__ldg(cm + (size_t)(y1i*W + x0 )*CLSC + chn));
        float v11 = __half2float(__ldg(cm + (size_t)(y1i*W + x1i)*CLSC + chn));
        acc += v00*(1.f-fx)*(1.f-fy) + v01*fx*(1.f-fy)
             + v10*(1.f-fx)*fy       + v11*fx*fy;
    }
    ob[((size_t)(n*NCLS + cls))*HW + rem] = acc;
}

// ---------------- launch ----------------
extern "C" void kernel_launch(void* const* d_in, const int* in_sizes, int n_in,
                              void* d_out, int out_size)
{
    (void)in_sizes; (void)n_in; (void)out_size;
    const float* reg_feat0 = (const float*)d_in[0];
    const float* reg_feat1 = (const float*)d_in[1];
    const float* cls_feat0 = (const float*)d_in[2];
    const float* cls_feat1 = (const float*)d_in[3];
    const float* anchor0   = (const float*)d_in[4];
    const float* anchor1   = (const float*)d_in[5];
    const float* dyn_w     = (const float*)d_in[6];
    const float* dyn_b     = (const float*)d_in[7];
    const float* reg_w     = (const float*)d_in[8];
    const float* cls_w     = (const float*)d_in[9];
    const float* cls_b     = (const float*)d_in[10];
    float* out = (float*)d_out;

    cudaFuncSetAttribute(mma_all_kernel,
                         cudaFuncAttributeMaxDynamicSharedMemorySize, UK_SMEM);

    split_w_kernel<<<(SW_TOTAL + 255)/256, 256>>>(dyn_w, reg_w, cls_w);
    split_all_kernel<<<dim3(475, 4, 8), dim3(32, 8)>>>(
        reg_feat0, reg_feat1, cls_feat0, cls_feat1);

    mma_all_kernel<<<2112, 128, UK_SMEM>>>(dyn_b);

    geom_all_kernel<<<(NPIX + 255)/256, 256>>>(anchor0, anchor1, out);
    cls_sample_kernel<<<(NPIX + SPB - 1)/SPB, SPB*NCLS>>>(cls_b, out);
}

// round 15
// speedup vs baseline: 1.5225x; 1.5225x over previous
#include <cuda_runtime.h>
#include <cuda_fp16.h>
#include <cstdint>

#define H0c 100
#define W0c 152
#define H1c 50
#define W1c 76
#define HW0 (H0c*W0c)          // 15200
#define HW1 (H1c*W1c)          // 3800
#define NB 2
#define CIN 256
#define DYNC 34
#define CLSC 720
#define NCLS 80
#define NPIX (NB*(HW0+HW1))    // 38000
#define NPIXP 38016            // 297*128
#define OCP 768
#define KDYN2 2304             // 9*256 (B_hi)

// padded (H+2, W+2) dims for dyn GEMM A-matrix
#define PH0 102
#define PW0 154
#define PH1 52
#define PW1 78
#define PAD0TOT (NB*PH0*PW0)            // 31416
#define PADTOT (PAD0TOT + NB*PH1*PW1)   // 39528

// border enumeration
#define BORD0 (2*PW0 + 2*(PH0-2))       // 508
#define BORD1 (2*PW1 + 2*(PH1-2))       // 256
#define NBORD (NB*BORD0 + NB*BORD1)     // 1528

#define O_CLS0 0
#define O_CLS1 (NB*NCLS*HW0)
#define O_CO0  (O_CLS1 + NB*NCLS*HW1)
#define O_CO1  (O_CO0 + NB*4*HW0)
#define O_RB0  (O_CO1 + NB*4*HW1)
#define O_RB1  (O_RB0 + NB*4*HW0)

// split_w index ranges
#define SW_DYN (64*9*256)               // 147456
#define SW_CLS (SW_DYN + OCP*CIN)       // 344064
#define SW_BORD (SW_CLS + NBORD*32)     // g_regS 256-wide -> 32 uint4/pix
#define SW_TOTAL (SW_BORD + 16*32)      // featS tail (16 pix * 32 uint4)

// ---------------- scratch ----------------
__device__ float g_pred[NPIX*DYNC];
__device__ float g_regmap[NPIX*4];
__device__ __half g_clsmap[(size_t)NPIXP*CLSC];
__device__ __align__(16) __half g_featS[(size_t)NPIXP*256];      // cls A hi [pix][256]
__device__ __align__(16) __half g_wclsS[(size_t)OCP*256];        // cls B_hi [oc][256]
__device__ __align__(16) __half g_regS[(size_t)PADTOT*256];      // dyn A hi [padpix][256]
__device__ __align__(16) __half g_wdynS[64*KDYN2];               // dyn B_hi [oc][9*256]

// ---------------- PTX helpers ----------------
__device__ __forceinline__ void cpa16(uint32_t d, const void* s) {
    asm volatile("cp.async.cg.shared.global [%0],[%1],16;\n" :: "r"(d), "l"(s));
}
#define CP_COMMIT() asm volatile("cp.async.commit_group;\n")
#define CP_WAIT1()  asm volatile("cp.async.wait_group 1;\n")
#define CP_WAIT0()  asm volatile("cp.async.wait_group 0;\n")

__device__ __forceinline__ void ldm_x4(uint32_t& r0, uint32_t& r1,
                                       uint32_t& r2, uint32_t& r3, uint32_t addr) {
    asm volatile("ldmatrix.sync.aligned.m8n8.x4.shared.b16 {%0,%1,%2,%3},[%4];"
                 : "=r"(r0), "=r"(r1), "=r"(r2), "=r"(r3) : "r"(addr));
}
__device__ __forceinline__ void mma_f16(float* c, uint32_t a0, uint32_t a1,
                                        uint32_t a2, uint32_t a3,
                                        uint32_t b0, uint32_t b1) {
    asm volatile("mma.sync.aligned.m16n8k16.row.col.f32.f16.f16.f32 "
                 "{%0,%1,%2,%3},{%4,%5,%6,%7},{%8,%9},{%0,%1,%2,%3};"
                 : "+f"(c[0]), "+f"(c[1]), "+f"(c[2]), "+f"(c[3])
                 : "r"(a0), "r"(a1), "r"(a2), "r"(a3), "r"(b0), "r"(b1));
}

// ---------------- merged weight split + border/tail zero ----------------
__global__ void split_w_kernel(const float* __restrict__ dyn_w,
                               const float* __restrict__ reg_w,
                               const float* __restrict__ cls_w) {
    int i = blockIdx.x*blockDim.x + threadIdx.x;
    if (i < SW_DYN) {
        int oc = i / (9*256);
        int rem = i - oc*9*256;
        int p = rem >> 8, c = rem & 255;
        float v = 0.f;
        if (oc < DYNC) v = dyn_w[(oc*CIN + c)*9 + p];
        else if (oc < 38 && p == 4) v = reg_w[(oc - DYNC)*CIN + c];
        g_wdynS[(size_t)oc*KDYN2 + p*256 + c] = __float2half(v);
    } else if (i < SW_CLS) {
        int j = i - SW_DYN;
        int oc = j >> 8, c = j & 255;
        float v = (oc < CLSC) ? cls_w[j] : 0.f;
        g_wclsS[(size_t)oc*256 + c] = __float2half(v);
    } else if (i < SW_BORD) {
        int b = i - SW_CLS;
        int bp = b >> 5, u = b & 31;
        int y, x, padBase, PWl;
        if (bp < NB*BORD0) {
            int n = bp / BORD0, k = bp - n*BORD0;
            padBase = n*PH0*PW0; PWl = PW0;
            if (k < PW0) { y = 0; x = k; }
            else if (k < 2*PW0) { y = PH0-1; x = k - PW0; }
            else { int k2 = k - 2*PW0; y = 1 + (k2 >> 1); x = (k2 & 1) ? (PW0-1) : 0; }
        } else {
            int b2 = bp - NB*BORD0;
            int n = b2 / BORD1, k = b2 - n*BORD1;
            padBase = PAD0TOT + n*PH1*PW1; PWl = PW1;
            if (k < PW1) { y = 0; x = k; }
            else if (k < 2*PW1) { y = PH1-1; x = k - PW1; }
            else { int k2 = k - 2*PW1; y = 1 + (k2 >> 1); x = (k2 & 1) ? (PW1-1) : 0; }
        }
        ((uint4*)g_regS)[(size_t)(padBase + y*PWl + x)*32 + u] = make_uint4(0,0,0,0);
    } else if (i < SW_TOTAL) {
        int j = i - SW_BORD;
        ((uint4*)g_featS)[(size_t)NPIX*32 + j] = make_uint4(0,0,0,0);
    }
}

// ---------------- merged feature transpose+split, 64-ch tiles, half2 writes ----------------
__global__ void split_all_kernel(const float* __restrict__ reg0,
                                 const float* __restrict__ reg1,
                                 const float* __restrict__ cls0,
                                 const float* __restrict__ cls1)
{
    __shared__ float t[64][33];
    int src = blockIdx.z >> 1;
    int n   = blockIdx.z & 1;
    int lvl = src & 1;
    int HW  = lvl ? HW1 : HW0;
    int pixbase = blockIdx.x*32;
    if (pixbase >= HW) return;
    const float* in = (src == 0) ? reg0 : (src == 1) ? reg1 : (src == 2) ? cls0 : cls1;

    int tx = threadIdx.x, ty = threadIdx.y;
    int chbase = blockIdx.y*64;
    int pix = pixbase + tx;
    #pragma unroll
    for (int j = 0; j < 8; j++) {
        int ch = ty + j*8;
        t[ch][tx] = (pix < HW) ? in[((size_t)(n*CIN + chbase + ch))*HW + pix] : 0.f;
    }
    __syncthreads();

    int u = ty*32 + tx;
    if (src >= 2) {   // cls -> g_featS (hi only)
        int base = lvl ? (NB*HW0 + n*HW1) : (n*HW0);
        #pragma unroll
        for (int k = 0; k < 4; k++) {
            int idx = u + k*256;
            int pr = idx >> 5, pi = idx & 31;
            int opix = pixbase + pr;
            if (opix < HW) {
                float v0 = t[pi*2][pr], v1 = t[pi*2+1][pr];
                __half* d = g_featS + (size_t)(base + opix)*256 + chbase + pi*2;
                *(__half2*)d = __halves2half2(__float2half(v0), __float2half(v1));
            }
        }
    } else {          // reg -> g_regS (padded, hi only)
        int W  = lvl ? W1c : W0c;
        int PW = lvl ? PW1 : PW0;
        int padBase = lvl ? (PAD0TOT + n*PH1*PW1) : (n*PH0*PW0);
        #pragma unroll
        for (int k = 0; k < 4; k++) {
            int idx = u + k*256;
            int pr = idx >> 5, pi = idx & 31;
            int opix = pixbase + pr;
            if (opix < HW) {
                int y = opix / W, x = opix - y*W;
                float v0 = t[pi*2][pr], v1 = t[pi*2+1][pr];
                __half* d = g_regS + (size_t)(padBase + (y+1)*PW + x + 1)*256 + chbase + pi*2;
                *(__half2*)d = __halves2half2(__float2half(v0), __float2half(v1));
            }
        }
    }
}

// ---------------- unified MMA kernel (128 threads, 4 warps, 3 CTAs/SM) ----------------
#define RS 144
#define A_STG (128*RS)       // 18432
#define DYN_B_STG (64*RS)    // 9216
#define CLS_B_STG (128*RS)   // 18432
#define UK_SMEM (2*A_STG + 2*CLS_B_STG)   // 73728

__global__ void __launch_bounds__(128, 3) mma_all_kernel(const float* __restrict__ dyn_b)
{
    extern __shared__ __align__(16) char sm[];
    int tid = threadIdx.x;
    int lane = tid & 31, wid = tid >> 5;
    int wm = wid & 1, wn = wid >> 1;
    int rA = tid >> 3, cA = tid & 7;

    uint32_t AsB = (uint32_t)__cvta_generic_to_shared(sm);

    if (blockIdx.x < 330) {
        // ---------- dyn: 128x64 tile, warp 64x32; K = 9*256 in 36 chunks ----------
        int bid = blockIdx.x;
        int lvl, n, tX, tY;
        if (bid < 260) { lvl = 0; n = bid/130; int t = bid - n*130; tY = t/10; tX = t - tY*10; }
        else { int b = bid - 260; lvl = 1; n = b/35; int t = b - n*35; tY = t/5; tX = t - tY*5; }
        int H  = lvl ? H1c : H0c;
        int W  = lvl ? W1c : W0c;
        int PW = lvl ? PW1 : PW0;
        int padBase = lvl ? (PAD0TOT + n*PH1*PW1) : (n*PH0*PW0);
        int gbase   = lvl ? (NB*HW0 + n*HW1) : (n*HW0);
        int y0 = tY*8, x0 = tX*16;

        int aPix[8];
        #pragma unroll
        for (int j = 0; j < 8; j++) {
            int r = rA + 16*j;
            int y = y0 + (r >> 4); if (y >= H) y = H - 1;
            int x = x0 + (r & 15); if (x >= W) x = W - 1;
            aPix[j] = padBase + (y + 1)*PW + x + 1;
        }

        uint32_t BsB = AsB + 2*A_STG;

        float acc[4][4][4];
        #pragma unroll
        for (int f = 0; f < 4; f++)
            #pragma unroll
            for (int j = 0; j < 4; j++)
                #pragma unroll
                for (int e = 0; e < 4; e++) acc[f][j][e] = 0.f;

        // zero smem B rows 48-63 (both stages); staging never writes them
        for (int z = tid; z < 2*16*9; z += 128) {
            int s = z / (16*9);
            int rr = 48 + ((z - s*16*9) / 9);
            int cc = (z % 9)*16;
            asm volatile("st.shared.v4.b32 [%0], {%1,%1,%1,%1};"
                         :: "r"(BsB + s*DYN_B_STG + (uint32_t)(rr*RS + cc)), "r"(0) : "memory");
        }

        // chunk q: p = q/4, kc = q%4
        #define DYN_LOAD(s, q) do { \
            int p_ = (q) >> 2, kc_ = (q) & 3; \
            int sh_ = (p_/3 - 1)*PW + (p_ - (p_/3)*3 - 1); \
            int ko_ = kc_*64 + cA*8; \
            _Pragma("unroll") \
            for (int j_ = 0; j_ < 8; j_++) \
                cpa16(AsB + (s)*A_STG + (uint32_t)((rA + 16*j_)*RS + cA*16), \
                      g_regS + (size_t)(aPix[j_] + sh_)*256 + ko_); \
            _Pragma("unroll") \
            for (int j_ = 0; j_ < 3; j_++)  /* B rows 0-47; 48-63 stay zero */ \
                cpa16(BsB + (s)*DYN_B_STG + (uint32_t)((rA + 16*j_)*RS + cA*16), \
                      g_wdynS + (size_t)(rA + 16*j_)*KDYN2 + p_*256 + ko_); \
        } while (0)

        __syncthreads();
        DYN_LOAD(0, 0);
        CP_COMMIT();

        #pragma unroll 1
        for (int q = 0; q < 36; q++) {
            int cur = q & 1;
            if (q < 35) {
                DYN_LOAD(cur ^ 1, q + 1);
                CP_COMMIT();
                CP_WAIT1();
            } else {
                CP_WAIT0();
            }
            __syncthreads();

            uint32_t abase = AsB + cur*A_STG + (uint32_t)((wm*64 + (lane & 15))*RS);
            uint32_t bbase = BsB + cur*DYN_B_STG + (uint32_t)((wn*32 + (lane & 15))*RS);
            uint32_t cofs0 = (uint32_t)((lane >> 4)*16);

            #pragma unroll
            for (int kk = 0; kk < 4; kk++) {
                uint32_t co = cofs0 + kk*32;
                uint32_t a[4][4];
                #pragma unroll
                for (int f = 0; f < 4; f++)
                    ldm_x4(a[f][0], a[f][1], a[f][2], a[f][3], abase + f*16*RS + co);
                uint32_t b[2][4];
                #pragma unroll
                for (int g = 0; g < 2; g++)
                    ldm_x4(b[g][0], b[g][1], b[g][2], b[g][3], bbase + g*16*RS + co);
                #pragma unroll
                for (int f = 0; f < 4; f++)
                    #pragma unroll
                    for (int g = 0; g < 2; g++) {
                        mma_f16(acc[f][2*g],   a[f][0], a[f][1], a[f][2], a[f][3],
                                b[g][0], b[g][2]);
                        mma_f16(acc[f][2*g+1], a[f][0], a[f][1], a[f][2], a[f][3],
                                b[g][1], b[g][3]);
                    }
            }
            __syncthreads();
        }

        int rowin = lane >> 2;
        int colin = (lane & 3)*2;
        #pragma unroll
        for (int f = 0; f < 4; f++) {
            #pragma unroll
            for (int half = 0; half < 2; half++) {
                int tr = wm*64 + f*16 + rowin + half*8;
                int y = y0 + (tr >> 4), x = x0 + (tr & 15);
                if (y < H && x < W) {
                    int gp = gbase + y*W + x;
                    #pragma unroll
                    for (int j = 0; j < 4; j++) {
                        int oc = wn*32 + j*8 + colin;
                        float v0 = acc[f][j][half*2];
                        float v1 = acc[f][j][half*2 + 1];
                        if (oc < DYNC) {
                            g_pred[(size_t)gp*DYNC + oc] = v0 + __ldg(dyn_b + oc);
                        } else if (oc < 38) {
                            g_regmap[(size_t)gp*4 + oc - DYNC] = v0;
                        }
                        int oc1 = oc + 1;
                        if (oc1 < DYNC) {
                            g_pred[(size_t)gp*DYNC + oc1] = v1 + __ldg(dyn_b + oc1);
                        } else if (oc1 < 38) {
                            g_regmap[(size_t)gp*4 + oc1 - DYNC] = v1;
                        }
                    }
                }
            }
        }
    } else {
        // ---------- cls: 128x128, warp 64x64; K=256 in 4 chunks ----------
        int bid = blockIdx.x - 330;
        int pixblk = bid % 297;
        int ocblk  = bid / 297;
        int pixbase = pixblk*128;
        int ocbase  = ocblk*128;

        const __half* Ag = g_featS + (size_t)pixbase*256;
        const __half* Bg = g_wclsS + (size_t)ocbase*256;

        uint32_t BsB = AsB + 2*A_STG;

        float acc[4][8][4];
        #pragma unroll
        for (int f = 0; f < 4; f++)
            #pragma unroll
            for (int j = 0; j < 8; j++)
                #pragma unroll
                for (int e = 0; e < 4; e++) acc[f][j][e] = 0.f;

        #define CLS_LOAD(s, bk) do { \
            int k_ = (bk)*64 + cA*8; \
            _Pragma("unroll") \
            for (int j_ = 0; j_ < 8; j_++) { \
                cpa16(AsB + (s)*A_STG + (uint32_t)((rA + 16*j_)*RS + cA*16), \
                      Ag + (size_t)(rA + 16*j_)*256 + k_); \
                cpa16(BsB + (s)*CLS_B_STG + (uint32_t)((rA + 16*j_)*RS + cA*16), \
                      Bg + (size_t)(rA + 16*j_)*256 + k_); \
            } \
        } while (0)

        CLS_LOAD(0, 0);
        CP_COMMIT();

        #pragma unroll 1
        for (int bk = 0; bk < 4; bk++) {
            int cur = bk & 1;
            if (bk < 3) {
                CLS_LOAD(cur ^ 1, bk + 1);
                CP_COMMIT();
                CP_WAIT1();
            } else {
                CP_WAIT0();
            }
            __syncthreads();

            uint32_t abase = AsB + cur*A_STG + (uint32_t)((wm*64 + (lane & 15))*RS);
            uint32_t bbase = BsB + cur*CLS_B_STG + (uint32_t)((wn*64 + (lane & 15))*RS);
            uint32_t cofs0 = (uint32_t)((lane >> 4)*16);

            #pragma unroll
            for (int kk = 0; kk < 4; kk++) {
                uint32_t co = cofs0 + kk*32;
                uint32_t a[4][4];
                #pragma unroll
                for (int f = 0; f < 4; f++)
                    ldm_x4(a[f][0], a[f][1], a[f][2], a[f][3], abase + f*16*RS + co);
                uint32_t b[4][4];
                #pragma unroll
                for (int g = 0; g < 4; g++)
                    ldm_x4(b[g][0], b[g][1], b[g][2], b[g][3], bbase + g*16*RS + co);
                #pragma unroll
                for (int f = 0; f < 4; f++)
                    #pragma unroll
                    for (int g = 0; g < 4; g++) {
                        mma_f16(acc[f][2*g],   a[f][0], a[f][1], a[f][2], a[f][3],
                                b[g][0], b[g][2]);
                        mma_f16(acc[f][2*g+1], a[f][0], a[f][1], a[f][2], a[f][3],
                                b[g][1], b[g][3]);
                    }
            }
            __syncthreads();
        }

        int rowin = lane >> 2;
        int colin = (lane & 3)*2;
        #pragma unroll
        for (int f = 0; f < 4; f++) {
            int pix = pixbase + wm*64 + f*16 + rowin;
            #pragma unroll
            for (int j = 0; j < 8; j++) {
                int oc = ocbase + wn*64 + j*8 + colin;
                if (oc < CLSC) {
                    __half* d0 = g_clsmap + (size_t)pix*CLSC + oc;
                    *(__half2*)d0 = __halves2half2(__float2half(acc[f][j][0]),
                                                   __float2half(acc[f][j][1]));
                    __half* d1 = g_clsmap + (size_t)(pix + 8)*CLSC + oc;
                    *(__half2*)d1 = __halves2half2(__float2half(acc[f][j][2]),
                                                   __float2half(acc[f][j][3]));
                }
            }
        }
    }
}

// ---------------- geometry + reg sampling (both levels, one launch) ----------------
__device__ __forceinline__ float bilin4(const float* __restrict__ rm,
                                        int H, int W, float px, float py, int chn)
{
    px = fminf(fmaxf(px, 0.f), (float)(W - 1));
    py = fminf(fmaxf(py, 0.f), (float)(H - 1));
    float xf = floorf(px), yf = floorf(py);
    float fx = px - xf, fy = py - yf;
    int x0 = (int)xf, y0 = (int)yf;
    int x1 = min(x0 + 1, W - 1), y1 = min(y0 + 1, H - 1);
    float v00 = rm[(y0*W + x0)*4 + chn];
    float v01 = rm[(y0*W + x1)*4 + chn];
    float v10 = rm[(y1*W + x0)*4 + chn];
    float v11 = rm[(y1*W + x1)*4 + chn];
    return v00*(1.f-fx)*(1.f-fy) + v01*fx*(1.f-fy)
         + v10*(1.f-fx)*fy       + v11*fx*fy;
}

__global__ void geom_all_kernel(const float* __restrict__ anchor0,
                                const float* __restrict__ anchor1,
                                float* __restrict__ out)
{
    int t = blockIdx.x*blockDim.x + threadIdx.x;
    if (t >= NPIX) return;
    int lvl = (t >= NB*HW0);
    int H, W, HW, n, rem;
    const float* anchor;
    float *oc_, *orb;
    if (!lvl) {
        HW = HW0; H = H0c; W = W0c;
        n = t / HW0; rem = t - n*HW0;
        anchor = anchor0; oc_ = out + O_CO0; orb = out + O_RB0;
    } else {
        int u = t - NB*HW0;
        HW = HW1; H = H1c; W = W1c;
        n = u / HW1; rem = u - n*HW1;
        anchor = anchor1; oc_ = out + O_CO1; orb = out + O_RB1;
    }

    const float* p = g_pred + (size_t)t*DYNC;
    float x1b = anchor[(n*4 + 0)*HW + rem] + p[0];
    float y1b = anchor[(n*4 + 1)*HW + rem] + p[1];
    float x2b = anchor[(n*4 + 2)*HW + rem] + p[2];
    float y2b = anchor[(n*4 + 3)*HW + rem] + p[3];
    float cx = 0.5f*(x1b + x2b), cy = 0.5f*(y1b + y2b);
    float th_h = (y2b - y1b)*0.25f;
    float th_w = (x2b - x1b)*0.25f;
    float b0 = p[4], b1 = p[5], b2 = p[6], b3 = p[7];
    float bc0 = b0 - (fmaxf(b0 - th_h, 0.f) + fminf(b0 + th_h, 0.f));
    float bc1 = b1 - (fmaxf(b1 - th_w, 0.f) + fminf(b1 + th_w, 0.f));
    float bc2 = b2 - (fmaxf(b2 - th_h, 0.f) + fminf(b2 + th_h, 0.f));
    float bc3 = b3 - (fmaxf(b3 - th_w, 0.f) + fminf(b3 + th_w, 0.f));

    float ptx[4] = {x1b, cx + bc1, x2b, cx + bc3};
    float pty[4] = {cy + bc0, y1b, cy + bc2, y2b};

    const float* rm = g_regmap + (size_t)(lvl ? (NB*HW0 + n*HW1) : (n*HW0))*4;
    float r[4];
    #pragma unroll
    for (int pc = 0; pc < 4; pc++)
        r[pc] = bilin4(rm, H, W, ptx[pc], pty[pc], pc);

    if (lvl) {
        const float* rml = g_regmap + (size_t)n*HW0*4;
        #pragma unroll
        for (int pc = 0; pc < 4; pc++) {
            float rl = 0.5f*bilin4(rml, H0c, W0c, 2.f*ptx[pc], 2.f*pty[pc], pc);
            float al = p[26 + 2*pc], ah = p[27 + 2*pc];
            float m = fmaxf(al, ah);
            float el = expf(al - m), eh = expf(ah - m);
            float inv = 1.f/(el + eh);
            r[pc] = (el*rl + eh*r[pc])*inv;
        }
    }

    oc_[(n*4 + 0)*HW + rem] = x1b;
    oc_[(n*4 + 1)*HW + rem] = y1b;
    oc_[(n*4 + 2)*HW + rem] = x2b;
    oc_[(n*4 + 3)*HW + rem] = y2b;
    orb[(n*4 + 0)*HW + rem] = x1b + r[0];
    orb[(n*4 + 1)*HW + rem] = y1b + r[1];
    orb[(n*4 + 2)*HW + rem] = x2b + r[2];
    orb[(n*4 + 3)*HW + rem] = y2b + r[3];
}

// ---------------- cls sampling: 4 pixels/block, 320 threads ----------------
#define SPB 4
__global__ void __launch_bounds__(SPB*NCLS) cls_sample_kernel(
    const float* __restrict__ cls_b, float* __restrict__ out)
{
    int t = blockIdx.x*SPB + threadIdx.x/NCLS;
    int cls = threadIdx.x % NCLS;
    if (t >= NPIX) return;

    int lvl = (t >= NB*HW0);
    int H, W, HW, n, rem, base;
    const float* coarse;
    float* ob;
    if (!lvl) {
        HW = HW0; H = H0c; W = W0c;
        n = t / HW0; rem = t - n*HW0;
        base = n*HW0;
        coarse = out + O_CO0; ob = out + O_CLS0;
    } else {
        int u = t - NB*HW0;
        HW = HW1; H = H1c; W = W1c;
        n = u / HW1; rem = u - n*HW1;
        base = NB*HW0 + n*HW1;
        coarse = out + O_CO1; ob = out + O_CLS1;
    }

    const float* p = g_pred + (size_t)t*DYNC;
    float x1b = coarse[(n*4 + 0)*HW + rem];
    float y1b = coarse[(n*4 + 1)*HW + rem];
    float x2b = coarse[(n*4 + 2)*HW + rem];
    float y2b = coarse[(n*4 + 3)*HW + rem];
    float X[3] = {x1b, 0.5f*(x1b + x2b), x2b};
    float Y[3] = {y1b, 0.5f*(y1b + y2b), y2b};

    float acc = cls_b[cls];
    const __half* cm = g_clsmap + (size_t)base*CLSC;

    #pragma unroll
    for (int pt = 0; pt < 9; pt++) {
        float px = X[pt/3] + p[8 + 2*pt];
        float py = Y[pt%3] + p[9 + 2*pt];
        px = fminf(fmaxf(px, 0.f), (float)(W - 1));
        py = fminf(fmaxf(py, 0.f), (float)(H - 1));
        float xf = floorf(px), yf = floorf(py);
        float fx = px - xf, fy = py - yf;
        int x0 = (int)xf, y0 = (int)yf;
        int x1i = min(x0 + 1, W - 1), y1i = min(y0 + 1, H - 1);
        int chn = pt*NCLS + cls;
        float v00 = __half2float(__ldg(cm + (size_t)(y0*W  + x0 )*CLSC + chn));
        float v01 = __half2float(__ldg(cm + (size_t)(y0*W  + x1i)*CLSC + chn));
        float v10 = __half2float(__ldg(cm + (size_t)(y1i*W + x0 )*CLSC + chn));
        float v11 = __half2float(__ldg(cm + (size_t)(y1i*W + x1i)*CLSC + chn));
        acc += v00*(1.f-fx)*(1.f-fy) + v01*fx*(1.f-fy)
             + v10*(1.f-fx)*fy       + v11*fx*fy;
    }
    ob[((size_t)(n*NCLS + cls))*HW + rem] = acc;
}

// ---------------- launch ----------------
extern "C" void kernel_launch(void* const* d_in, const int* in_sizes, int n_in,
                              void* d_out, int out_size)
{
    (void)in_sizes; (void)n_in; (void)out_size;
    const float* reg_feat0 = (const float*)d_in[0];
    const float* reg_feat1 = (const float*)d_in[1];
    const float* cls_feat0 = (const float*)d_in[2];
    const float* cls_feat1 = (const float*)d_in[3];
    const float* anchor0   = (const float*)d_in[4];
    const float* anchor1   = (const float*)d_in[5];
    const float* dyn_w     = (const float*)d_in[6];
    const float* dyn_b     = (const float*)d_in[7];
    const float* reg_w     = (const float*)d_in[8];
    const float* cls_w     = (const float*)d_in[9];
    const float* cls_b     = (const float*)d_in[10];
    float* out = (float*)d_out;

    cudaFuncSetAttribute(mma_all_kernel,
                         cudaFuncAttributeMaxDynamicSharedMemorySize, UK_SMEM);

    split_w_kernel<<<(SW_TOTAL + 255)/256, 256>>>(dyn_w, reg_w, cls_w);
    split_all_kernel<<<dim3(475, 4, 8), dim3(32, 8)>>>(
        reg_feat0, reg_feat1, cls_feat0, cls_feat1);

    mma_all_kernel<<<2112, 128, UK_SMEM>>>(dyn_b);

    geom_all_kernel<<<(NPIX + 255)/256, 256>>>(anchor0, anchor1, out);
    cls_sample_kernel<<<(NPIX + SPB - 1)/SPB, SPB*NCLS>>>(cls_b, out);
}

// round 16
// speedup vs baseline: 1.8189x; 1.1947x over previous
#include <cuda_runtime.h>
#include <cuda_fp16.h>
#include <cstdint>

#define H0c 100
#define W0c 152
#define H1c 50
#define W1c 76
#define HW0 (H0c*W0c)          // 15200
#define HW1 (H1c*W1c)          // 3800
#define NB 2
#define CIN 256
#define DYNC 34
#define CLSC 720
#define NCLS 80
#define NPIX (NB*(HW0+HW1))    // 38000
#define NPIXP 38016            // 297*128
#define OCP 768
#define KDYN2 2304             // 9*256 (B_hi)

// padded (H+2, W+2) dims for dyn GEMM A-matrix
#define PH0 102
#define PW0 154
#define PH1 52
#define PW1 78
#define PAD0TOT (NB*PH0*PW0)            // 31416
#define PADTOT (PAD0TOT + NB*PH1*PW1)   // 39528

// border enumeration
#define BORD0 (2*PW0 + 2*(PH0-2))       // 508
#define BORD1 (2*PW1 + 2*(PH1-2))       // 256
#define NBORD (NB*BORD0 + NB*BORD1)     // 1528

#define O_CLS0 0
#define O_CLS1 (NB*NCLS*HW0)
#define O_CO0  (O_CLS1 + NB*NCLS*HW1)
#define O_CO1  (O_CO0 + NB*4*HW0)
#define O_RB0  (O_CO1 + NB*4*HW1)
#define O_RB1  (O_RB0 + NB*4*HW0)

// split_w index ranges
#define SW_DYN (64*9*256)               // 147456
#define SW_CLS (SW_DYN + OCP*CIN)       // 344064
#define SW_BORD (SW_CLS + NBORD*32)     // g_regS 256-wide -> 32 uint4/pix
#define SW_TOTAL (SW_BORD + 16*32)      // featS tail (16 pix * 32 uint4)

// ---------------- scratch ----------------
__device__ float g_pred[NPIX*DYNC];
__device__ float g_regmap[NPIX*4];
__device__ __half g_clsmap[(size_t)NPIXP*CLSC];
__device__ __align__(16) __half g_featS[(size_t)NPIXP*256];      // cls A hi [pix][256]
__device__ __align__(16) __half g_wclsS[(size_t)OCP*256];        // cls B_hi [oc][256]
__device__ __align__(16) __half g_regS[(size_t)PADTOT*256];      // dyn A hi [padpix][256]
__device__ __align__(16) __half g_wdynS[64*KDYN2];               // dyn B_hi [oc][9*256]

// ---------------- PTX helpers ----------------
__device__ __forceinline__ void cpa16(uint32_t d, const void* s) {
    asm volatile("cp.async.cg.shared.global [%0],[%1],16;\n" :: "r"(d), "l"(s));
}
#define CP_COMMIT() asm volatile("cp.async.commit_group;\n")
#define CP_WAIT1()  asm volatile("cp.async.wait_group 1;\n")
#define CP_WAIT0()  asm volatile("cp.async.wait_group 0;\n")

__device__ __forceinline__ void ldm_x4(uint32_t& r0, uint32_t& r1,
                                       uint32_t& r2, uint32_t& r3, uint32_t addr) {
    asm volatile("ldmatrix.sync.aligned.m8n8.x4.shared.b16 {%0,%1,%2,%3},[%4];"
                 : "=r"(r0), "=r"(r1), "=r"(r2), "=r"(r3) : "r"(addr));
}
__device__ __forceinline__ void mma_f16(float* c, uint32_t a0, uint32_t a1,
                                        uint32_t a2, uint32_t a3,
                                        uint32_t b0, uint32_t b1) {
    asm volatile("mma.sync.aligned.m16n8k16.row.col.f32.f16.f16.f32 "
                 "{%0,%1,%2,%3},{%4,%5,%6,%7},{%8,%9},{%0,%1,%2,%3};"
                 : "+f"(c[0]), "+f"(c[1]), "+f"(c[2]), "+f"(c[3])
                 : "r"(a0), "r"(a1), "r"(a2), "r"(a3), "r"(b0), "r"(b1));
}

// ---------------- merged weight split + border/tail zero ----------------
__global__ void split_w_kernel(const float* __restrict__ dyn_w,
                               const float* __restrict__ reg_w,
                               const float* __restrict__ cls_w) {
    int i = blockIdx.x*blockDim.x + threadIdx.x;
    if (i < SW_DYN) {
        int oc = i / (9*256);
        int rem = i - oc*9*256;
        int p = rem >> 8, c = rem & 255;
        float v = 0.f;
        if (oc < DYNC) v = dyn_w[(oc*CIN + c)*9 + p];
        else if (oc < 38 && p == 4) v = reg_w[(oc - DYNC)*CIN + c];
        g_wdynS[(size_t)oc*KDYN2 + p*256 + c] = __float2half(v);
    } else if (i < SW_CLS) {
        int j = i - SW_DYN;
        int oc = j >> 8, c = j & 255;
        float v = (oc < CLSC) ? cls_w[j] : 0.f;
        g_wclsS[(size_t)oc*256 + c] = __float2half(v);
    } else if (i < SW_BORD) {
        int b = i - SW_CLS;
        int bp = b >> 5, u = b & 31;
        int y, x, padBase, PWl;
        if (bp < NB*BORD0) {
            int n = bp / BORD0, k = bp - n*BORD0;
            padBase = n*PH0*PW0; PWl = PW0;
            if (k < PW0) { y = 0; x = k; }
            else if (k < 2*PW0) { y = PH0-1; x = k - PW0; }
            else { int k2 = k - 2*PW0; y = 1 + (k2 >> 1); x = (k2 & 1) ? (PW0-1) : 0; }
        } else {
            int b2 = bp - NB*BORD0;
            int n = b2 / BORD1, k = b2 - n*BORD1;
            padBase = PAD0TOT + n*PH1*PW1; PWl = PW1;
            if (k < PW1) { y = 0; x = k; }
            else if (k < 2*PW1) { y = PH1-1; x = k - PW1; }
            else { int k2 = k - 2*PW1; y = 1 + (k2 >> 1); x = (k2 & 1) ? (PW1-1) : 0; }
        }
        ((uint4*)g_regS)[(size_t)(padBase + y*PWl + x)*32 + u] = make_uint4(0,0,0,0);
    } else if (i < SW_TOTAL) {
        int j = i - SW_BORD;
        ((uint4*)g_featS)[(size_t)NPIX*32 + j] = make_uint4(0,0,0,0);
    }
}

// ---------------- merged feature transpose+split, 64-ch tiles, half2 writes ----------------
__global__ void split_all_kernel(const float* __restrict__ reg0,
                                 const float* __restrict__ reg1,
                                 const float* __restrict__ cls0,
                                 const float* __restrict__ cls1)
{
    __shared__ float t[64][33];
    int src = blockIdx.z >> 1;
    int n   = blockIdx.z & 1;
    int lvl = src & 1;
    int HW  = lvl ? HW1 : HW0;
    int pixbase = blockIdx.x*32;
    if (pixbase >= HW) return;
    const float* in = (src == 0) ? reg0 : (src == 1) ? reg1 : (src == 2) ? cls0 : cls1;

    int tx = threadIdx.x, ty = threadIdx.y;
    int chbase = blockIdx.y*64;
    int pix = pixbase + tx;
    #pragma unroll
    for (int j = 0; j < 8; j++) {
        int ch = ty + j*8;
        t[ch][tx] = (pix < HW) ? in[((size_t)(n*CIN + chbase + ch))*HW + pix] : 0.f;
    }
    __syncthreads();

    int u = ty*32 + tx;
    if (src >= 2) {   // cls -> g_featS (hi only)
        int base = lvl ? (NB*HW0 + n*HW1) : (n*HW0);
        #pragma unroll
        for (int k = 0; k < 4; k++) {
            int idx = u + k*256;
            int pr = idx >> 5, pi = idx & 31;
            int opix = pixbase + pr;
            if (opix < HW) {
                float v0 = t[pi*2][pr], v1 = t[pi*2+1][pr];
                __half* d = g_featS + (size_t)(base + opix)*256 + chbase + pi*2;
                *(__half2*)d = __halves2half2(__float2half(v0), __float2half(v1));
            }
        }
    } else {          // reg -> g_regS (padded, hi only)
        int W  = lvl ? W1c : W0c;
        int PW = lvl ? PW1 : PW0;
        int padBase = lvl ? (PAD0TOT + n*PH1*PW1) : (n*PH0*PW0);
        #pragma unroll
        for (int k = 0; k < 4; k++) {
            int idx = u + k*256;
            int pr = idx >> 5, pi = idx & 31;
            int opix = pixbase + pr;
            if (opix < HW) {
                int y = opix / W, x = opix - y*W;
                float v0 = t[pi*2][pr], v1 = t[pi*2+1][pr];
                __half* d = g_regS + (size_t)(padBase + (y+1)*PW + x + 1)*256 + chbase + pi*2;
                *(__half2*)d = __halves2half2(__float2half(v0), __float2half(v1));
            }
        }
    }
}

// ---------------- unified MMA kernel (128 threads, 4 warps, 3 CTAs/SM) ----------------
#define RS 144
#define A_STG (128*RS)       // 18432
#define DYN_B_STG (64*RS)    // 9216
#define CLS_B_STG (128*RS)   // 18432
#define UK_SMEM (2*A_STG + 2*CLS_B_STG)   // 73728

__global__ void __launch_bounds__(128, 3) mma_all_kernel(const float* __restrict__ dyn_b)
{
    extern __shared__ __align__(16) char sm[];
    int tid = threadIdx.x;
    int lane = tid & 31, wid = tid >> 5;
    int wm = wid & 1, wn = wid >> 1;
    int rA = tid >> 3, cA = tid & 7;

    uint32_t AsB = (uint32_t)__cvta_generic_to_shared(sm);

    if (blockIdx.x < 330) {
        // ---------- dyn: 128x64 tile, warp 64x32; K = 9*256 in 36 chunks ----------
        int bid = blockIdx.x;
        int lvl, n, tX, tY;
        if (bid < 260) { lvl = 0; n = bid/130; int t = bid - n*130; tY = t/10; tX = t - tY*10; }
        else { int b = bid - 260; lvl = 1; n = b/35; int t = b - n*35; tY = t/5; tX = t - tY*5; }
        int H  = lvl ? H1c : H0c;
        int W  = lvl ? W1c : W0c;
        int PW = lvl ? PW1 : PW0;
        int padBase = lvl ? (PAD0TOT + n*PH1*PW1) : (n*PH0*PW0);
        int gbase   = lvl ? (NB*HW0 + n*HW1) : (n*HW0);
        int y0 = tY*8, x0 = tX*16;

        int aPix[8];
        #pragma unroll
        for (int j = 0; j < 8; j++) {
            int r = rA + 16*j;
            int y = y0 + (r >> 4); if (y >= H) y = H - 1;
            int x = x0 + (r & 15); if (x >= W) x = W - 1;
            aPix[j] = padBase + (y + 1)*PW + x + 1;
        }

        uint32_t BsB = AsB + 2*A_STG;

        float acc[4][4][4];
        #pragma unroll
        for (int f = 0; f < 4; f++)
            #pragma unroll
            for (int j = 0; j < 4; j++)
                #pragma unroll
                for (int e = 0; e < 4; e++) acc[f][j][e] = 0.f;

        // zero smem B rows 48-63 (both stages); staging never writes them
        for (int z = tid; z < 2*16*9; z += 128) {
            int s = z / (16*9);
            int rr = 48 + ((z - s*16*9) / 9);
            int cc = (z % 9)*16;
            asm volatile("st.shared.v4.b32 [%0], {%1,%1,%1,%1};"
                         :: "r"(BsB + s*DYN_B_STG + (uint32_t)(rr*RS + cc)), "r"(0) : "memory");
        }

        // chunk q: p = q/4, kc = q%4
        #define DYN_LOAD(s, q) do { \
            int p_ = (q) >> 2, kc_ = (q) & 3; \
            int sh_ = (p_/3 - 1)*PW + (p_ - (p_/3)*3 - 1); \
            int ko_ = kc_*64 + cA*8; \
            _Pragma("unroll") \
            for (int j_ = 0; j_ < 8; j_++) \
                cpa16(AsB + (s)*A_STG + (uint32_t)((rA + 16*j_)*RS + cA*16), \
                      g_regS + (size_t)(aPix[j_] + sh_)*256 + ko_); \
            _Pragma("unroll") \
            for (int j_ = 0; j_ < 3; j_++)  /* B rows 0-47; 48-63 stay zero */ \
                cpa16(BsB + (s)*DYN_B_STG + (uint32_t)((rA + 16*j_)*RS + cA*16), \
                      g_wdynS + (size_t)(rA + 16*j_)*KDYN2 + p_*256 + ko_); \
        } while (0)

        __syncthreads();
        DYN_LOAD(0, 0);
        CP_COMMIT();

        #pragma unroll 1
        for (int q = 0; q < 36; q++) {
            int cur = q & 1;
            if (q < 35) {
                DYN_LOAD(cur ^ 1, q + 1);
                CP_COMMIT();
                CP_WAIT1();
            } else {
                CP_WAIT0();
            }
            __syncthreads();

            uint32_t abase = AsB + cur*A_STG + (uint32_t)((wm*64 + (lane & 15))*RS);
            uint32_t bbase = BsB + cur*DYN_B_STG + (uint32_t)((wn*32 + (lane & 15))*RS);
            uint32_t cofs0 = (uint32_t)((lane >> 4)*16);

            #pragma unroll
            for (int kk = 0; kk < 4; kk++) {
                uint32_t co = cofs0 + kk*32;
                uint32_t a[4][4];
                #pragma unroll
                for (int f = 0; f < 4; f++)
                    ldm_x4(a[f][0], a[f][1], a[f][2], a[f][3], abase + f*16*RS + co);
                uint32_t b[2][4];
                #pragma unroll
                for (int g = 0; g < 2; g++)
                    ldm_x4(b[g][0], b[g][1], b[g][2], b[g][3], bbase + g*16*RS + co);
                #pragma unroll
                for (int f = 0; f < 4; f++)
                    #pragma unroll
                    for (int g = 0; g < 2; g++) {
                        mma_f16(acc[f][2*g],   a[f][0], a[f][1], a[f][2], a[f][3],
                                b[g][0], b[g][2]);
                        mma_f16(acc[f][2*g+1], a[f][0], a[f][1], a[f][2], a[f][3],
                                b[g][1], b[g][3]);
                    }
            }
            __syncthreads();
        }

        int rowin = lane >> 2;
        int colin = (lane & 3)*2;
        #pragma unroll
        for (int f = 0; f < 4; f++) {
            #pragma unroll
            for (int half = 0; half < 2; half++) {
                int tr = wm*64 + f*16 + rowin + half*8;
                int y = y0 + (tr >> 4), x = x0 + (tr & 15);
                if (y < H && x < W) {
                    int gp = gbase + y*W + x;
                    #pragma unroll
                    for (int j = 0; j < 4; j++) {
                        int oc = wn*32 + j*8 + colin;
                        float v0 = acc[f][j][half*2];
                        float v1 = acc[f][j][half*2 + 1];
                        if (oc < DYNC) {
                            g_pred[(size_t)gp*DYNC + oc] = v0 + __ldg(dyn_b + oc);
                        } else if (oc < 38) {
                            g_regmap[(size_t)gp*4 + oc - DYNC] = v0;
                        }
                        int oc1 = oc + 1;
                        if (oc1 < DYNC) {
                            g_pred[(size_t)gp*DYNC + oc1] = v1 + __ldg(dyn_b + oc1);
                        } else if (oc1 < 38) {
                            g_regmap[(size_t)gp*4 + oc1 - DYNC] = v1;
                        }
                    }
                }
            }
        }
    } else {
        // ---------- cls: 128x128, warp 64x64; K=256 in 4 chunks ----------
        int bid = blockIdx.x - 330;
        int pixblk = bid % 297;
        int ocblk  = bid / 297;
        int pixbase = pixblk*128;
        int ocbase  = ocblk*128;

        const __half* Ag = g_featS + (size_t)pixbase*256;
        const __half* Bg = g_wclsS + (size_t)ocbase*256;

        uint32_t BsB = AsB + 2*A_STG;

        float acc[4][8][4];
        #pragma unroll
        for (int f = 0; f < 4; f++)
            #pragma unroll
            for (int j = 0; j < 8; j++)
                #pragma unroll
                for (int e = 0; e < 4; e++) acc[f][j][e] = 0.f;

        #define CLS_LOAD(s, bk) do { \
            int k_ = (bk)*64 + cA*8; \
            _Pragma("unroll") \
            for (int j_ = 0; j_ < 8; j_++) { \
                cpa16(AsB + (s)*A_STG + (uint32_t)((rA + 16*j_)*RS + cA*16), \
                      Ag + (size_t)(rA + 16*j_)*256 + k_); \
                cpa16(BsB + (s)*CLS_B_STG + (uint32_t)((rA + 16*j_)*RS + cA*16), \
                      Bg + (size_t)(rA + 16*j_)*256 + k_); \
            } \
        } while (0)

        CLS_LOAD(0, 0);
        CP_COMMIT();

        #pragma unroll 1
        for (int bk = 0; bk < 4; bk++) {
            int cur = bk & 1;
            if (bk < 3) {
                CLS_LOAD(cur ^ 1, bk + 1);
                CP_COMMIT();
                CP_WAIT1();
            } else {
                CP_WAIT0();
            }
            __syncthreads();

            uint32_t abase = AsB + cur*A_STG + (uint32_t)((wm*64 + (lane & 15))*RS);
            uint32_t bbase = BsB + cur*CLS_B_STG + (uint32_t)((wn*64 + (lane & 15))*RS);
            uint32_t cofs0 = (uint32_t)((lane >> 4)*16);

            #pragma unroll
            for (int kk = 0; kk < 4; kk++) {
                uint32_t co = cofs0 + kk*32;
                uint32_t a[4][4];
                #pragma unroll
                for (int f = 0; f < 4; f++)
                    ldm_x4(a[f][0], a[f][1], a[f][2], a[f][3], abase + f*16*RS + co);
                uint32_t b[4][4];
                #pragma unroll
                for (int g = 0; g < 4; g++)
                    ldm_x4(b[g][0], b[g][1], b[g][2], b[g][3], bbase + g*16*RS + co);
                #pragma unroll
                for (int f = 0; f < 4; f++)
                    #pragma unroll
                    for (int g = 0; g < 4; g++) {
                        mma_f16(acc[f][2*g],   a[f][0], a[f][1], a[f][2], a[f][3],
                                b[g][0], b[g][2]);
                        mma_f16(acc[f][2*g+1], a[f][0], a[f][1], a[f][2], a[f][3],
                                b[g][1], b[g][3]);
                    }
            }
            __syncthreads();
        }

        int rowin = lane >> 2;
        int colin = (lane & 3)*2;
        #pragma unroll
        for (int f = 0; f < 4; f++) {
            int pix = pixbase + wm*64 + f*16 + rowin;
            #pragma unroll
            for (int j = 0; j < 8; j++) {
                int oc = ocbase + wn*64 + j*8 + colin;
                if (oc < CLSC) {
                    __half* d0 = g_clsmap + (size_t)pix*CLSC + oc;
                    *(__half2*)d0 = __halves2half2(__float2half(acc[f][j][0]),
                                                   __float2half(acc[f][j][1]));
                    __half* d1 = g_clsmap + (size_t)(pix + 8)*CLSC + oc;
                    *(__half2*)d1 = __halves2half2(__float2half(acc[f][j][2]),
                                                   __float2half(acc[f][j][3]));
                }
            }
        }
    }
}

// ---------------- geometry + reg sampling (both levels, one launch) ----------------
__device__ __forceinline__ float bilin4(const float* __restrict__ rm,
                                        int H, int W, float px, float py, int chn)
{
    px = fminf(fmaxf(px, 0.f), (float)(W - 1));
    py = fminf(fmaxf(py, 0.f), (float)(H - 1));
    float xf = floorf(px), yf = floorf(py);
    float fx = px - xf, fy = py - yf;
    int x0 = (int)xf, y0 = (int)yf;
    int x1 = min(x0 + 1, W - 1), y1 = min(y0 + 1, H - 1);
    float v00 = rm[(y0*W + x0)*4 + chn];
    float v01 = rm[(y0*W + x1)*4 + chn];
    float v10 = rm[(y1*W + x0)*4 + chn];
    float v11 = rm[(y1*W + x1)*4 + chn];
    return v00*(1.f-fx)*(1.f-fy) + v01*fx*(1.f-fy)
         + v10*(1.f-fx)*fy       + v11*fx*fy;
}

__global__ void geom_all_kernel(const float* __restrict__ anchor0,
                                const float* __restrict__ anchor1,
                                float* __restrict__ out)
{
    int t = blockIdx.x*blockDim.x + threadIdx.x;
    if (t >= NPIX) return;
    int lvl = (t >= NB*HW0);
    int H, W, HW, n, rem;
    const float* anchor;
    float *oc_, *orb;
    if (!lvl) {
        HW = HW0; H = H0c; W = W0c;
        n = t / HW0; rem = t - n*HW0;
        anchor = anchor0; oc_ = out + O_CO0; orb = out + O_RB0;
    } else {
        int u = t - NB*HW0;
        HW = HW1; H = H1c; W = W1c;
        n = u / HW1; rem = u - n*HW1;
        anchor = anchor1; oc_ = out + O_CO1; orb = out + O_RB1;
    }

    const float* p = g_pred + (size_t)t*DYNC;
    float x1b = anchor[(n*4 + 0)*HW + rem] + p[0];
    float y1b = anchor[(n*4 + 1)*HW + rem] + p[1];
    float x2b = anchor[(n*4 + 2)*HW + rem] + p[2];
    float y2b = anchor[(n*4 + 3)*HW + rem] + p[3];
    float cx = 0.5f*(x1b + x2b), cy = 0.5f*(y1b + y2b);
    float th_h = (y2b - y1b)*0.25f;
    float th_w = (x2b - x1b)*0.25f;
    float b0 = p[4], b1 = p[5], b2 = p[6], b3 = p[7];
    float bc0 = b0 - (fmaxf(b0 - th_h, 0.f) + fminf(b0 + th_h, 0.f));
    float bc1 = b1 - (fmaxf(b1 - th_w, 0.f) + fminf(b1 + th_w, 0.f));
    float bc2 = b2 - (fmaxf(b2 - th_h, 0.f) + fminf(b2 + th_h, 0.f));
    float bc3 = b3 - (fmaxf(b3 - th_w, 0.f) + fminf(b3 + th_w, 0.f));

    float ptx[4] = {x1b, cx + bc1, x2b, cx + bc3};
    float pty[4] = {cy + bc0, y1b, cy + bc2, y2b};

    const float* rm = g_regmap + (size_t)(lvl ? (NB*HW0 + n*HW1) : (n*HW0))*4;
    float r[4];
    #pragma unroll
    for (int pc = 0; pc < 4; pc++)
        r[pc] = bilin4(rm, H, W, ptx[pc], pty[pc], pc);

    if (lvl) {
        const float* rml = g_regmap + (size_t)n*HW0*4;
        #pragma unroll
        for (int pc = 0; pc < 4; pc++) {
            float rl = 0.5f*bilin4(rml, H0c, W0c, 2.f*ptx[pc], 2.f*pty[pc], pc);
            float al = p[26 + 2*pc], ah = p[27 + 2*pc];
            float m = fmaxf(al, ah);
            float el = expf(al - m), eh = expf(ah - m);
            float inv = 1.f/(el + eh);
            r[pc] = (el*rl + eh*r[pc])*inv;
        }
    }

    oc_[(n*4 + 0)*HW + rem] = x1b;
    oc_[(n*4 + 1)*HW + rem] = y1b;
    oc_[(n*4 + 2)*HW + rem] = x2b;
    oc_[(n*4 + 3)*HW + rem] = y2b;
    orb[(n*4 + 0)*HW + rem] = x1b + r[0];
    orb[(n*4 + 1)*HW + rem] = y1b + r[1];
    orb[(n*4 + 2)*HW + rem] = x2b + r[2];
    orb[(n*4 + 3)*HW + rem] = y2b + r[3];
}

// ---------------- cls sampling: 8 pixels/block, 40 threads/pixel (half2), smem transpose ----------------
#define SPB 8
#define TPP 40
__global__ void __launch_bounds__(SPB*TPP) cls_sample_kernel(
    const float* __restrict__ cls_b, float* __restrict__ out)
{
    __shared__ float sout[NCLS][SPB];

    int t0 = blockIdx.x*SPB;
    int tp = threadIdx.x / TPP;       // pixel in block
    int c2 = threadIdx.x % TPP;       // class pair (2*c2, 2*c2+1)
    int t  = t0 + tp;

    // all pixels in block share segment (boundaries are multiples of 8)
    int lvl = (t0 >= NB*HW0);
    int H, W, HW, n, rem0, base;
    const float* coarse;
    float* ob;
    if (!lvl) {
        HW = HW0; H = H0c; W = W0c;
        n = t0 / HW0; rem0 = t0 - n*HW0;
        base = n*HW0;
        coarse = out + O_CO0; ob = out + O_CLS0;
    } else {
        int u = t0 - NB*HW0;
        HW = HW1; H = H1c; W = W1c;
        n = u / HW1; rem0 = u - n*HW1;
        base = NB*HW0 + n*HW1;
        coarse = out + O_CO1; ob = out + O_CLS1;
    }
    int rem = rem0 + tp;

    const float* p = g_pred + (size_t)t*DYNC;
    float x1b = coarse[(n*4 + 0)*HW + rem];
    float y1b = coarse[(n*4 + 1)*HW + rem];
    float x2b = coarse[(n*4 + 2)*HW + rem];
    float y2b = coarse[(n*4 + 3)*HW + rem];
    float X[3] = {x1b, 0.5f*(x1b + x2b), x2b};
    float Y[3] = {y1b, 0.5f*(y1b + y2b), y2b};

    float bias0 = cls_b[2*c2], bias1 = cls_b[2*c2 + 1];
    float acc0 = bias0, acc1 = bias1;
    const __half* cm = g_clsmap + (size_t)base*CLSC;

    #pragma unroll
    for (int pt = 0; pt < 9; pt++) {
        float px = X[pt/3] + p[8 + 2*pt];
        float py = Y[pt%3] + p[9 + 2*pt];
        px = fminf(fmaxf(px, 0.f), (float)(W - 1));
        py = fminf(fmaxf(py, 0.f), (float)(H - 1));
        float xf = floorf(px), yf = floorf(py);
        float fx = px - xf, fy = py - yf;
        int x0 = (int)xf, y0 = (int)yf;
        int x1i = min(x0 + 1, W - 1), y1i = min(y0 + 1, H - 1);
        int chn = pt*NCLS + 2*c2;
        float2 v00 = __half22float2(*(const __half2*)(cm + (size_t)(y0*W  + x0 )*CLSC + chn));
        float2 v01 = __half22float2(*(const __half2*)(cm + (size_t)(y0*W  + x1i)*CLSC + chn));
        float2 v10 = __half22float2(*(const __half2*)(cm + (size_t)(y1i*W + x0 )*CLSC + chn));
        float2 v11 = __half22float2(*(const __half2*)(cm + (size_t)(y1i*W + x1i)*CLSC + chn));
        float w00 = (1.f-fx)*(1.f-fy), w01 = fx*(1.f-fy);
        float w10 = (1.f-fx)*fy,       w11 = fx*fy;
        acc0 += v00.x*w00 + v01.x*w01 + v10.x*w10 + v11.x*w11;
        acc1 += v00.y*w00 + v01.y*w01 + v10.y*w10 + v11.y*w11;
    }
    sout[2*c2][tp] = acc0;
    sout[2*c2 + 1][tp] = acc1;
    __syncthreads();

    // coalesced write: 8 consecutive pixels per class row
    for (int idx = threadIdx.x; idx < NCLS*SPB; idx += SPB*TPP) {
        int cls = idx >> 3, px = idx & 7;
        ob[((size_t)(n*NCLS + cls))*HW + rem0 + px] = sout[cls][px];
    }
}

// ---------------- launch ----------------
extern "C" void kernel_launch(void* const* d_in, const int* in_sizes, int n_in,
                              void* d_out, int out_size)
{
    (void)in_sizes; (void)n_in; (void)out_size;
    const float* reg_feat0 = (const float*)d_in[0];
    const float* reg_feat1 = (const float*)d_in[1];
    const float* cls_feat0 = (const float*)d_in[2];
    const float* cls_feat1 = (const float*)d_in[3];
    const float* anchor0   = (const float*)d_in[4];
    const float* anchor1   = (const float*)d_in[5];
    const float* dyn_w     = (const float*)d_in[6];
    const float* dyn_b     = (const float*)d_in[7];
    const float* reg_w     = (const float*)d_in[8];
    const float* cls_w     = (const float*)d_in[9];
    const float* cls_b     = (const float*)d_in[10];
    float* out = (float*)d_out;

    cudaFuncSetAttribute(mma_all_kernel,
                         cudaFuncAttributeMaxDynamicSharedMemorySize, UK_SMEM);

    split_w_kernel<<<(SW_TOTAL + 255)/256, 256>>>(dyn_w, reg_w, cls_w);
    split_all_kernel<<<dim3(475, 4, 8), dim3(32, 8)>>>(
        reg_feat0, reg_feat1, cls_feat0, cls_feat1);

    mma_all_kernel<<<2112, 128, UK_SMEM>>>(dyn_b);

    geom_all_kernel<<<(NPIX + 255)/256, 256>>>(anchor0, anchor1, out);
    cls_sample_kernel<<<NPIX/SPB, SPB*TPP>>>(cls_b, out);
}